// round 1
// baseline (speedup 1.0000x reference)
#include <cuda_runtime.h>

#define N_NODES 100000
#define N_EDGES 1600000
#define N_GRAPHS 512
#define N_REL 4
#define N_TYPES 13
#define HID 128
#define WCOLS 640   // [root(128) | rel0..3 (4*128)]
#define BN_EPS 1e-5f
#define L2_EPS 1e-12f

// ---------------- device scratch (allocation-free rule: __device__ globals) --
__device__ __align__(16) float  g_hA[N_NODES * HID];        // layer buffer A
__device__ __align__(16) float  g_hB[N_NODES * HID];        // layer buffer B
__device__ __align__(16) float  g_hr[(size_t)N_NODES * WCOLS]; // layer-1 GEMM out
__device__ __align__(16) float  g_T0[N_TYPES * WCOLS];      // layer-0 table
__device__ __align__(16) float  g_W1[128 * WCOLS];          // packed layer-1 weights
__device__ int    g_ntype[N_NODES];
__device__ int    g_cnt4[N_NODES * 4];
__device__ float  g_winv[N_NODES * 4];
__device__ int    g_deg[N_NODES];
__device__ int    g_offs[N_NODES + 1];
__device__ int    g_cursor[N_NODES];
__device__ int    g_elist[N_EDGES];                         // packed (src<<2)|rel
__device__ double g_stats[256];                             // [sum(128) | sumsq(128)]
__device__ __align__(16) float g_pool[N_GRAPHS * HID];
__device__ int    g_gcnt[N_GRAPHS];

// ---------------- utility zero kernels --------------------------------------
__global__ void k_zero_prep() {
    int i = blockIdx.x * blockDim.x + threadIdx.x;
    if (i < N_NODES * 4) g_cnt4[i] = 0;
}
__global__ void k_zero_stats() {
    int i = threadIdx.x;
    if (i < 256) g_stats[i] = 0.0;
}
__global__ void k_zero_pool() {
    int i = blockIdx.x * blockDim.x + threadIdx.x;
    if (i < N_GRAPHS * HID) g_pool[i] = 0.f;
    if (i < N_GRAPHS) g_gcnt[i] = 0;
}

// ---------------- node type = argmax over one-hot [N,13] --------------------
__global__ void k_ntype(const float* __restrict__ x) {
    int n = blockIdx.x * blockDim.x + threadIdx.x;
    if (n >= N_NODES) return;
    const float* row = x + (size_t)n * N_TYPES;
    int t = 0; float best = row[0];
    #pragma unroll
    for (int i = 1; i < N_TYPES; i++) {
        float v = row[i];
        if (v > best) { best = v; t = i; }
    }
    g_ntype[n] = t;
}

// ---------------- per-(dst,rel) in-degree counts -----------------------------
__global__ void k_count(const int* __restrict__ ei, const int* __restrict__ etype) {
    int e = blockIdx.x * blockDim.x + threadIdx.x;
    if (e >= N_EDGES) return;
    int dst = ei[N_EDGES + e];
    int et  = etype[e];
    atomicAdd(&g_cnt4[dst * 4 + et], 1);
}
__global__ void k_winv() {
    int i = blockIdx.x * blockDim.x + threadIdx.x;
    if (i < N_NODES * 4)
        g_winv[i] = 1.f / fmaxf((float)g_cnt4[i], 1.f);
}
__global__ void k_deg() {
    int n = blockIdx.x * blockDim.x + threadIdx.x;
    if (n >= N_NODES) return;
    g_deg[n] = g_cnt4[n*4] + g_cnt4[n*4+1] + g_cnt4[n*4+2] + g_cnt4[n*4+3];
}

// ---------------- single-block exclusive scan for CSR offsets ----------------
__global__ void k_scan() {
    __shared__ int sh[1024];
    __shared__ int run;
    int tid = threadIdx.x;
    if (tid == 0) run = 0;
    __syncthreads();
    for (int base = 0; base < N_NODES; base += 1024) {
        int i = base + tid;
        int v = (i < N_NODES) ? g_deg[i] : 0;
        sh[tid] = v;
        __syncthreads();
        #pragma unroll
        for (int off = 1; off < 1024; off <<= 1) {
            int t = (tid >= off) ? sh[tid - off] : 0;
            __syncthreads();
            sh[tid] += t;
            __syncthreads();
        }
        if (i < N_NODES) g_offs[i] = run + sh[tid] - v;   // exclusive
        __syncthreads();
        if (tid == 1023) run += sh[1023];
        __syncthreads();
    }
    if (tid == 0) g_offs[N_NODES] = run;
}
__global__ void k_cursor() {
    int n = blockIdx.x * blockDim.x + threadIdx.x;
    if (n < N_NODES) g_cursor[n] = g_offs[n];
}
__global__ void k_fill(const int* __restrict__ ei, const int* __restrict__ etype) {
    int e = blockIdx.x * blockDim.x + threadIdx.x;
    if (e >= N_EDGES) return;
    int src = ei[e];
    int dst = ei[N_EDGES + e];
    int et  = etype[e];
    int pos = atomicAdd(&g_cursor[dst], 1);
    g_elist[pos] = (src << 2) | et;
}

// ---------------- layer-0 table: T0[t][c] = emb[t] @ {Wroot0|Wrel0[r]} (+bias root)
__global__ void k_t0(const float* __restrict__ emb, const float* __restrict__ Wrel,
                     const float* __restrict__ Wroot, const float* __restrict__ bias) {
    int i = blockIdx.x * blockDim.x + threadIdx.x;
    if (i >= N_TYPES * WCOLS) return;
    int t = i / WCOLS, c = i % WCOLS;
    float s;
    if (c < 128) {
        s = bias[c];
        #pragma unroll 8
        for (int k = 0; k < 128; k++) s += emb[t*128 + k] * Wroot[k*128 + c];
    } else {
        int r = (c - 128) >> 7, j = (c - 128) & 127;
        const float* wr = Wrel + r * 16384;
        s = 0.f;
        #pragma unroll 8
        for (int k = 0; k < 128; k++) s += emb[t*128 + k] * wr[k*128 + j];
    }
    g_T0[i] = s;
}

// ---------------- pack layer-1 weights into [128, 640] -----------------------
__global__ void k_packW1(const float* __restrict__ Wrel, const float* __restrict__ Wroot) {
    int i = blockIdx.x * blockDim.x + threadIdx.x;
    if (i >= 128 * WCOLS) return;
    int k = i / WCOLS, c = i % WCOLS;
    float v;
    if (c < 128) v = Wroot[16384 + k*128 + c];                      // layer 1 root
    else {
        int r = (c - 128) >> 7, j = (c - 128) & 127;
        v = Wrel[(4 + r) * 16384 + k*128 + j];                      // layer 1 rel r
    }
    g_W1[i] = v;
}

// ---------------- GEMM: g_hr[N,640] = g_hA[N,128] @ g_W1[128,640] (+bias root)
__global__ __launch_bounds__(256) void k_gemm(const float* __restrict__ bias) {
    __shared__ float As[64][132];
    __shared__ float Bs[128][68];
    const int tid  = threadIdx.x;
    const int row0 = blockIdx.x * 64;
    const int col0 = blockIdx.y * 64;

    #pragma unroll
    for (int i = 0; i < 8; i++) {
        int f = tid + i * 256;
        int r = f >> 5, c4 = f & 31;
        int gr = row0 + r;
        float4 v = make_float4(0.f, 0.f, 0.f, 0.f);
        if (gr < N_NODES) v = *reinterpret_cast<const float4*>(&g_hA[(size_t)gr * 128 + c4 * 4]);
        *reinterpret_cast<float4*>(&As[r][c4 * 4]) = v;
    }
    #pragma unroll
    for (int i = 0; i < 8; i++) {
        int f = tid + i * 256;
        int r = f >> 4, c4 = f & 15;
        float4 v = *reinterpret_cast<const float4*>(&g_W1[r * WCOLS + col0 + c4 * 4]);
        *reinterpret_cast<float4*>(&Bs[r][c4 * 4]) = v;
    }
    __syncthreads();

    const int tx = tid & 15, ty = tid >> 4;
    float acc[4][4];
    #pragma unroll
    for (int m = 0; m < 4; m++)
        #pragma unroll
        for (int n = 0; n < 4; n++) acc[m][n] = 0.f;

    #pragma unroll 8
    for (int k = 0; k < 128; k++) {
        float4 b = *reinterpret_cast<const float4*>(&Bs[k][tx * 4]);
        float a0 = As[ty*4 + 0][k];
        float a1 = As[ty*4 + 1][k];
        float a2 = As[ty*4 + 2][k];
        float a3 = As[ty*4 + 3][k];
        acc[0][0] += a0*b.x; acc[0][1] += a0*b.y; acc[0][2] += a0*b.z; acc[0][3] += a0*b.w;
        acc[1][0] += a1*b.x; acc[1][1] += a1*b.y; acc[1][2] += a1*b.z; acc[1][3] += a1*b.w;
        acc[2][0] += a2*b.x; acc[2][1] += a2*b.y; acc[2][2] += a2*b.z; acc[2][3] += a2*b.w;
        acc[3][0] += a3*b.x; acc[3][1] += a3*b.y; acc[3][2] += a3*b.z; acc[3][3] += a3*b.w;
    }

    #pragma unroll
    for (int m = 0; m < 4; m++) {
        int gr = row0 + ty * 4 + m;
        if (gr >= N_NODES) continue;
        #pragma unroll
        for (int n = 0; n < 4; n++) {
            int gc = col0 + tx * 4 + n;
            float v = acc[m][n] + (gc < 128 ? bias[gc] : 0.f);
            g_hr[(size_t)gr * WCOLS + gc] = v;
        }
    }
}

// ---------------- layer-0 aggregation: table lookup gather -------------------
__global__ __launch_bounds__(256) void k_agg0() {
    int node = (blockIdx.x * 256 + threadIdx.x) >> 5;
    int lane = threadIdx.x & 31;
    if (node >= N_NODES) return;
    float w0 = g_winv[node*4+0], w1 = g_winv[node*4+1];
    float w2 = g_winv[node*4+2], w3 = g_winv[node*4+3];
    float4 acc = *reinterpret_cast<const float4*>(&g_T0[g_ntype[node] * WCOLS + lane * 4]);
    int beg = g_offs[node], end = g_offs[node + 1];
    for (int e = beg; e < end; e++) {
        int p = g_elist[e];
        int src = p >> 2, et = p & 3;
        int ts = g_ntype[src];
        float4 m = *reinterpret_cast<const float4*>(&g_T0[ts * WCOLS + 128 + et * 128 + lane * 4]);
        float w = (et == 0) ? w0 : (et == 1) ? w1 : (et == 2) ? w2 : w3;
        acc.x += m.x * w; acc.y += m.y * w; acc.z += m.z * w; acc.w += m.w * w;
    }
    *reinterpret_cast<float4*>(&g_hA[(size_t)node * 128 + lane * 4]) = acc;
}

// ---------------- layer-1 aggregation: gather from g_hr ----------------------
__global__ __launch_bounds__(256) void k_agg1() {
    int node = (blockIdx.x * 256 + threadIdx.x) >> 5;
    int lane = threadIdx.x & 31;
    if (node >= N_NODES) return;
    float w0 = g_winv[node*4+0], w1 = g_winv[node*4+1];
    float w2 = g_winv[node*4+2], w3 = g_winv[node*4+3];
    float4 acc = *reinterpret_cast<const float4*>(&g_hr[(size_t)node * WCOLS + lane * 4]);
    int beg = g_offs[node], end = g_offs[node + 1];
    for (int e = beg; e < end; e++) {
        int p = g_elist[e];
        int src = p >> 2, et = p & 3;
        float4 m = *reinterpret_cast<const float4*>(
            &g_hr[(size_t)src * WCOLS + 128 + et * 128 + lane * 4]);
        float w = (et == 0) ? w0 : (et == 1) ? w1 : (et == 2) ? w2 : w3;
        acc.x += m.x * w; acc.y += m.y * w; acc.z += m.z * w; acc.w += m.w * w;
    }
    *reinterpret_cast<float4*>(&g_hB[(size_t)node * 128 + lane * 4]) = acc;
}

// ---------------- BN stats: per-column sum & sumsq (double atomics) ----------
__global__ void k_bnstats(int which) {
    const float* h = which ? g_hB : g_hA;
    int col = threadIdx.x;             // 128 threads
    double s = 0.0, s2 = 0.0;
    for (int r = blockIdx.x; r < N_NODES; r += gridDim.x) {
        float v = h[(size_t)r * 128 + col];
        s  += (double)v;
        s2 += (double)v * (double)v;
    }
    atomicAdd(&g_stats[col], s);
    atomicAdd(&g_stats[128 + col], s2);
}

// ---------------- BN apply + PReLU + row L2-normalize (in place) -------------
__global__ __launch_bounds__(256) void k_bnapply(int which, const float* __restrict__ gamma,
                                                 const float* __restrict__ beta,
                                                 const float* __restrict__ pa) {
    float* h = which ? g_hB : g_hA;
    int node = (blockIdx.x * 256 + threadIdx.x) >> 5;
    int lane = threadIdx.x & 31;
    if (node >= N_NODES) return;
    float alpha = pa[0];
    float4 v = *reinterpret_cast<const float4*>(&h[(size_t)node * 128 + lane * 4]);
    float vin[4] = { v.x, v.y, v.z, v.w };
    float y[4]; float ss = 0.f;
    #pragma unroll
    for (int q = 0; q < 4; q++) {
        int c = lane * 4 + q;
        double mu  = g_stats[c] * (1.0 / N_NODES);
        double var = g_stats[128 + c] * (1.0 / N_NODES) - mu * mu;
        float sc = rsqrtf((float)var + BN_EPS) * gamma[c];
        float val = (vin[q] - (float)mu) * sc + beta[c];
        val = (val >= 0.f) ? val : alpha * val;
        y[q] = val;
        ss += val * val;
    }
    #pragma unroll
    for (int o = 16; o; o >>= 1) ss += __shfl_xor_sync(0xffffffffu, ss, o);
    float inv = 1.f / fmaxf(sqrtf(ss), L2_EPS);
    float4 o4 = make_float4(y[0]*inv, y[1]*inv, y[2]*inv, y[3]*inv);
    *reinterpret_cast<float4*>(&h[(size_t)node * 128 + lane * 4]) = o4;
}

// ---------------- global mean pool (atomics) ----------------------------------
__global__ __launch_bounds__(256) void k_pool(const int* __restrict__ batch) {
    int node = (blockIdx.x * 256 + threadIdx.x) >> 5;
    int lane = threadIdx.x & 31;
    if (node >= N_NODES) return;
    int g = batch[node];
    float4 v = *reinterpret_cast<const float4*>(&g_hB[(size_t)node * 128 + lane * 4]);
    atomicAdd(&g_pool[g * 128 + lane * 4 + 0], v.x);
    atomicAdd(&g_pool[g * 128 + lane * 4 + 1], v.y);
    atomicAdd(&g_pool[g * 128 + lane * 4 + 2], v.z);
    atomicAdd(&g_pool[g * 128 + lane * 4 + 3], v.w);
    if (lane == 0) atomicAdd(&g_gcnt[g], 1);
}

// ---------------- MLP head: one block per graph -------------------------------
__global__ __launch_bounds__(256) void k_mlp(const float* __restrict__ fc1w, const float* __restrict__ fc1b,
                                             const float* __restrict__ fc2w, const float* __restrict__ fc2b,
                                             const float* __restrict__ ow,  const float* __restrict__ ob,
                                             float* __restrict__ out) {
    int g = blockIdx.x;
    int t = threadIdx.x;                 // 256 threads
    __shared__ float sg[128], s1[256], s2[128], red[256];
    float invc = 1.f / fmaxf((float)g_gcnt[g], 1.f);
    if (t < 128) sg[t] = g_pool[g * 128 + t] * invc;
    __syncthreads();
    float s = fc1b[t];
    #pragma unroll 8
    for (int k = 0; k < 128; k++) s += sg[k] * fc1w[k * 256 + t];
    s1[t] = fmaxf(s, 0.f);
    __syncthreads();
    if (t < 128) {
        float s2v = fc2b[t];
        #pragma unroll 8
        for (int k = 0; k < 256; k++) s2v += s1[k] * fc2w[k * 128 + t];
        s2[t] = fmaxf(s2v, 0.f);
    }
    __syncthreads();
    red[t] = (t < 128) ? s2[t] * ow[t] : 0.f;
    __syncthreads();
    for (int o = 128; o > 0; o >>= 1) {
        if (t < o) red[t] += red[t + o];
        __syncthreads();
    }
    if (t == 0) out[g] = red[0] + ob[0];
}

// =============================================================================
extern "C" void kernel_launch(void* const* d_in, const int* in_sizes, int n_in,
                              void* d_out, int out_size) {
    const float* x      = (const float*)d_in[0];
    const int*   ei     = (const int*)  d_in[1];
    const int*   etype  = (const int*)  d_in[2];
    const int*   batch  = (const int*)  d_in[3];
    const float* emb    = (const float*)d_in[4];
    const float* Wrel   = (const float*)d_in[5];   // [2,4,128,128]
    const float* Wroot  = (const float*)d_in[6];   // [2,128,128]
    const float* cbias  = (const float*)d_in[7];   // [2,128]
    const float* gamma  = (const float*)d_in[8];   // [2,128]
    const float* beta   = (const float*)d_in[9];   // [2,128]
    const float* pa     = (const float*)d_in[10];  // [2]
    const float* fc1w   = (const float*)d_in[11];
    const float* fc1b   = (const float*)d_in[12];
    const float* fc2w   = (const float*)d_in[13];
    const float* fc2b   = (const float*)d_in[14];
    const float* ow     = (const float*)d_in[15];
    const float* ob     = (const float*)d_in[16];
    float* out = (float*)d_out;

    const int TB = 256;
    // ---- graph structure (recomputed every call: deterministic work) ----
    k_zero_prep<<<(N_NODES * 4 + TB - 1) / TB, TB>>>();
    k_ntype<<<(N_NODES + TB - 1) / TB, TB>>>(x);
    k_count<<<(N_EDGES + TB - 1) / TB, TB>>>(ei, etype);
    k_winv<<<(N_NODES * 4 + TB - 1) / TB, TB>>>();
    k_deg<<<(N_NODES + TB - 1) / TB, TB>>>();
    k_scan<<<1, 1024>>>();
    k_cursor<<<(N_NODES + TB - 1) / TB, TB>>>();
    k_fill<<<(N_EDGES + TB - 1) / TB, TB>>>(ei, etype);

    const int nodeWarpBlocks = (N_NODES * 32 + TB - 1) / TB;

    // ---- layer 0 ----
    k_t0<<<(N_TYPES * WCOLS + TB - 1) / TB, TB>>>(emb, Wrel, Wroot, cbias);
    k_agg0<<<nodeWarpBlocks, TB>>>();
    k_zero_stats<<<1, 256>>>();
    k_bnstats<<<512, 128>>>(0);
    k_bnapply<<<nodeWarpBlocks, TB>>>(0, gamma, beta, pa);

    // ---- layer 1 ----
    k_packW1<<<(128 * WCOLS + TB - 1) / TB, TB>>>(Wrel, Wroot);
    dim3 gemmGrid((N_NODES + 63) / 64, WCOLS / 64);
    k_gemm<<<gemmGrid, 256>>>(cbias + 128);
    k_agg1<<<nodeWarpBlocks, TB>>>();
    k_zero_stats<<<1, 256>>>();
    k_bnstats<<<512, 128>>>(1);
    k_bnapply<<<nodeWarpBlocks, TB>>>(1, gamma + 128, beta + 128, pa + 1);

    // ---- pool + MLP ----
    k_zero_pool<<<(N_GRAPHS * HID + TB - 1) / TB, TB>>>();
    k_pool<<<nodeWarpBlocks, TB>>>(batch);
    k_mlp<<<N_GRAPHS, 256>>>(fc1w, fc1b, fc2w, fc2b, ow, ob, out);
}